// round 10
// baseline (speedup 1.0000x reference)
#include <cuda_runtime.h>
#include <cstdint>
#include <cfloat>
#include <math.h>

#define NPTS 8192
#define DIM 64
#define KNN 90
#define NCAT 8
#define NTRIES 50
#define TOLR 1e-5f
#define CAND_CAP 1024

// scratch (device globals: allocation-free kernel_launch)
__device__ float g_d2[(size_t)NPTS * NPTS];   // 256 MB pairwise d2 (diagonal = FLT_MAX)
__device__ float g_dist[NPTS * KNN];
__device__ int   g_lab[NPTS * KNN];

// ---------------------------------------------------------------- GEMM stage
#define BM 128
#define BN 128
#define KPAD 65   // 64 + 1 pad: conflict-free LDS for strided frags

__device__ __forceinline__ unsigned long long pack2(float lo, float hi) {
    unsigned long long r;
    asm("mov.b64 %0, {%1, %2};" : "=l"(r) : "f"(lo), "f"(hi));
    return r;
}
__device__ __forceinline__ void unpack2(unsigned long long v, float& lo, float& hi) {
    asm("mov.b64 {%0, %1}, %2;" : "=f"(lo), "=f"(hi) : "l"(v));
}
__device__ __forceinline__ void fma2(unsigned long long& d,
                                     unsigned long long a, unsigned long long b) {
    // packed fp32x2 FMA: exact fp32, independent lanes, 2x FFMA-pipe throughput
    asm("fma.rn.f32x2 %0, %1, %2, %0;" : "+l"(d) : "l"(a), "l"(b));
}

// XLA-emulating row norm: jnp.sum(x*x, -1): products individually rounded
// (no fma), float2-vectorized lane partials, then shfl tree.
__device__ __forceinline__ float xla_row_sq(const float* rowp, int lane) {
    float x0 = rowp[2 * lane];
    float x1 = rowp[2 * lane + 1];
    float s = __fadd_rn(__fmul_rn(x0, x0), __fmul_rn(x1, x1));
    #pragma unroll
    for (int off = 16; off > 0; off >>= 1)
        s = __fadd_rn(s, __shfl_down_sync(0xffffffffu, s, off));
    return __shfl_sync(0xffffffffu, s, 0);
}

__global__ void __launch_bounds__(256, 2) gemm_d2_kernel(const float* __restrict__ x) {
    extern __shared__ float smem[];
    float* As  = smem;                    // [BM][KPAD]
    float* Bs  = smem + BM * KPAD;        // [BN][KPAD]
    float* sqA = Bs + BN * KPAD;          // [BM]
    float* sqB = sqA + BM;                // [BN]

    const int tid = threadIdx.x;
    const int bm = blockIdx.y * BM;
    const int bn = blockIdx.x * BN;

    // coalesced global load: float4 per thread, 16 threads cover one 64-col row
    const int c4 = tid & 15;   // float4 index within row
    const int rb = tid >> 4;   // 0..15
    #pragma unroll
    for (int it = 0; it < 8; ++it) {
        int r = rb + it * 16;
        float4 av = *reinterpret_cast<const float4*>(x + (size_t)(bm + r) * DIM + c4 * 4);
        float4 bv = *reinterpret_cast<const float4*>(x + (size_t)(bn + r) * DIM + c4 * 4);
        float* ap = As + r * KPAD + c4 * 4;
        ap[0] = av.x; ap[1] = av.y; ap[2] = av.z; ap[3] = av.w;
        float* bp = Bs + r * KPAD + c4 * 4;
        bp[0] = bv.x; bp[1] = bv.y; bp[2] = bv.z; bp[3] = bv.w;
    }
    __syncthreads();

    // norms with XLA-matching arithmetic (warp per row)
    {
        const int lane = tid & 31;
        const int wrp  = tid >> 5;
        #pragma unroll
        for (int it = 0; it < 16; ++it) {
            int r = wrp + it * 8;
            float sa = xla_row_sq(As + r * KPAD, lane);
            float sb = xla_row_sq(Bs + r * KPAD, lane);
            if (lane == 0) { sqA[r] = sa; sqB[r] = sb; }
        }
    }
    __syncthreads();

    // 8x8 micro-tile, strided mapping (row = ty+16i, col = tx+16j):
    // a-frag LDS is a 32-lane broadcast, b-frag stride-65 is conflict-free.
    // Accumulators are packed f32x2 pairs (columns 2j, 2j+1) — same sequential
    // ascending-k fp32 accumulation per column, so d2 is bit-identical to the
    // scalar-FFMA version.
    const int tx = tid & 15;
    const int ty = tid >> 4;

    unsigned long long acc[8][4];
    #pragma unroll
    for (int i = 0; i < 8; ++i)
        #pragma unroll
        for (int j = 0; j < 4; ++j) acc[i][j] = 0ULL;

    #pragma unroll 4
    for (int k = 0; k < DIM; ++k) {
        float a[8], b[8];
        #pragma unroll
        for (int i = 0; i < 8; ++i) a[i] = As[(ty + 16 * i) * KPAD + k];
        #pragma unroll
        for (int j = 0; j < 8; ++j) b[j] = Bs[(tx + 16 * j) * KPAD + k];
        unsigned long long bp[4];
        #pragma unroll
        for (int j = 0; j < 4; ++j) bp[j] = pack2(b[2 * j], b[2 * j + 1]);
        #pragma unroll
        for (int i = 0; i < 8; ++i) {
            unsigned long long ap = pack2(a[i], a[i]);
            #pragma unroll
            for (int j = 0; j < 4; ++j) fma2(acc[i][j], ap, bp[j]);
        }
    }

    #pragma unroll
    for (int i = 0; i < 8; ++i) {
        int m = ty + 16 * i;
        int gm = bm + m;
        float sm = sqA[m];
        float* orow = g_d2 + (size_t)gm * NPTS + bn;
        #pragma unroll
        for (int j = 0; j < 4; ++j) {
            float d0, d1;
            unpack2(acc[i][j], d0, d1);
            int n0 = tx + 16 * (2 * j);
            int n1 = tx + 16 * (2 * j + 1);
            // reference elementwise order: (sq_i + sq_j) - 2*mm, then max(.,0)
            float v0 = __fsub_rn(__fadd_rn(sm, sqB[n0]), __fmul_rn(2.f, d0));
            float v1 = __fsub_rn(__fadd_rn(sm, sqB[n1]), __fmul_rn(2.f, d1));
            v0 = fmaxf(v0, 0.f);
            v1 = fmaxf(v1, 0.f);
            if (gm == bn + n0) v0 = FLT_MAX;   // exclude self
            if (gm == bn + n1) v1 = FLT_MAX;
            orow[n0] = v0;
            orow[n1] = v1;
        }
    }
}

// ------------------------------------------------------------- select stage
// one block per row: stage the row ONCE in shared (single DRAM pass), then
// radix-refine to a candidate superset and bitonic-sort by (key, idx) —
// exactly jax.lax.top_k order. The sort makes the refine self-correcting.
__global__ void __launch_bounds__(256) select_kernel(const int* __restrict__ batch_id) {
    __shared__ unsigned skey[NPTS];                 // 32 KB — staged row
    __shared__ unsigned hist[256];
    __shared__ unsigned sc[256];
    __shared__ unsigned long long cand[CAND_CAP];   // 8 KB
    __shared__ unsigned s_prefix, s_kneed, s_bincnt, s_cnt;

    const int row  = blockIdx.x;
    const int tid  = threadIdx.x;
    const int lane = tid & 31;

    // single coalesced DRAM pass
    const uint4* rp = reinterpret_cast<const uint4*>(g_d2 + (size_t)row * NPTS);
    #pragma unroll
    for (int it = 0; it < 8; ++it) {
        int q = tid + it * 256;
        uint4 v = rp[q];
        skey[q * 4 + 0] = v.x;
        skey[q * 4 + 1] = v.y;
        skey[q * 4 + 2] = v.z;
        skey[q * 4 + 3] = v.w;
    }
    __syncthreads();

    // --- refine 8-bit radix levels from the top until candidates fit ---
    unsigned prefix = 0;
    unsigned kneed  = KNN;
    int shift = 32;
    for (int lvl = 0; lvl < 4; ++lvl) {
        shift -= 8;
        hist[tid] = 0;
        __syncthreads();
        for (int j = tid; j < NPTS; j += 256) {
            unsigned key = skey[j];
            bool isc = (lvl == 0) || ((key >> (shift + 8)) == (prefix >> (shift + 8)));
            // match_any aggregation: exponent-clustered bins would serialize
            // plain shared atomics 32-way
            unsigned bin = isc ? ((key >> shift) & 255u) : (256u + (unsigned)lane);
            unsigned mm = __match_any_sync(0xffffffffu, bin);
            if (isc && lane == (__ffs(mm) - 1))
                atomicAdd(&hist[bin], (unsigned)__popc(mm));
        }
        __syncthreads();
        unsigned hv = hist[tid];
        sc[tid] = hv;
        __syncthreads();
        for (int off = 1; off < 256; off <<= 1) {
            unsigned t = (tid >= off) ? sc[tid - off] : 0u;
            __syncthreads();
            sc[tid] += t;
            __syncthreads();
        }
        unsigned inc = sc[tid], exc = inc - hv;
        if (kneed > exc && kneed <= inc) {
            s_prefix = prefix | ((unsigned)tid << shift);
            s_kneed  = kneed - exc;
            s_bincnt = hv;
        }
        __syncthreads();
        prefix = s_prefix;
        kneed  = s_kneed;
        unsigned total = (KNN - kneed) + s_bincnt;   // |keys < bin| + |keys in bin|
        __syncthreads();
        if (total <= CAND_CAP - 32 || shift == 0) break;
    }

    // --- gather candidate superset: all keys with high bits <= refined bin ---
    if (tid == 0) s_cnt = 0;
    __syncthreads();
    const unsigned prefHigh = prefix >> shift;
    for (int j = tid; j < NPTS; j += 256) {
        unsigned key = skey[j];
        if ((key >> shift) <= prefHigh) {
            unsigned pos = atomicAdd(&s_cnt, 1u);
            if (pos < CAND_CAP)
                cand[pos] = ((unsigned long long)key << 32) | (unsigned)j;
        }
    }
    __syncthreads();
    unsigned cnt = s_cnt;
    if (cnt > CAND_CAP) cnt = CAND_CAP;

    // --- bitonic sort ascending by (key, idx) packed in 64 bits ---
    const int sortN = (cnt <= 256) ? 256 : CAND_CAP;
    for (int i = tid; i < sortN; i += 256)
        if (i >= (int)cnt) cand[i] = 0xFFFFFFFFFFFFFFFFull;
    __syncthreads();
    for (int k = 2; k <= sortN; k <<= 1) {
        for (int j = k >> 1; j > 0; j >>= 1) {
            for (int i = tid; i < sortN; i += 256) {
                int ix = i ^ j;
                if (ix > i) {
                    unsigned long long a = cand[i], b = cand[ix];
                    bool up = ((i & k) == 0);
                    if ((a > b) == up) { cand[i] = b; cand[ix] = a; }
                }
            }
            __syncthreads();
        }
    }

    // --- emit first KNN in exact top_k order ---
    if (tid < KNN) {
        unsigned long long v = cand[tid];
        unsigned key = (unsigned)(v >> 32);
        int idx = (int)(v & 0xFFFFFFFFu);
        g_dist[row * KNN + tid] = __fsqrt_rn(__uint_as_float(key));
        g_lab[row * KNN + tid]  = batch_id[idx];
    }
}

// --------------------------------------------------------- beta search stage
__device__ __forceinline__ float warp_sum(float v) {
    #pragma unroll
    for (int o = 16; o > 0; o >>= 1) v += __shfl_xor_sync(0xffffffffu, v, o);
    return v;
}

// FTZ exp: XLA compiles GPU f32 with flush-to-zero — exp results that would be
// subnormal flush to 0. Load-bearing: rows whose solution beta sits past the
// subnormal cliff hit Psum==0 -> H==0 sentinel in the reference.
__device__ __forceinline__ float exp_ftz(float a) {
    float v = expf(a);
    if (v < 1.17549435e-38f) v = 0.f;   // flush subnormal result
    return v;
}

__device__ __forceinline__ void hbeta_eval(const float d[3], const bool val[3],
                                           float beta, float p[3],
                                           float& Psum, float& H) {
    float ls = 0.f, lds = 0.f;
    #pragma unroll
    for (int t = 0; t < 3; ++t) {
        float pv = val[t] ? exp_ftz(-d[t] * beta) : 0.f;
        p[t] = pv;
        ls  += pv;
        lds += d[t] * pv;
    }
    Psum   = warp_sum(ls);
    float S = warp_sum(lds);
    H = (Psum > 0.f) ? (logf(Psum) + beta * __fdiv_rn(S, Psum)) : 0.f;
}

__global__ void __launch_bounds__(128) beta_kernel(float* __restrict__ out) {
    const int warp = threadIdx.x >> 5;
    const int lane = threadIdx.x & 31;
    const int row  = blockIdx.x * 4 + warp;

    float d[3]; int lb[3]; bool val[3];
    #pragma unroll
    for (int t = 0; t < 3; ++t) {
        int kk = lane + 32 * t;
        val[t] = (kk < KNN);
        d[t]  = val[t] ? g_dist[row * KNN + kk] : 0.f;
        lb[t] = val[t] ? g_lab[row * KNN + kk]  : -1;
    }

    const float logU = logf(30.0f);
    float beta = 1.f, bmin = 0.f, bmax = 0.f;
    bool hasMin = false, hasMax = false;
    float p[3], Psum, H;

    hbeta_eval(d, val, beta, p, Psum, H);
    float Hdiff = H - logU;
    for (int it = 0; it < NTRIES; ++it) {
        if (fabsf(Hdiff) < TOLR) break;     // == reference "done" freeze
        if (Hdiff > 0.f) {
            bmin = beta; hasMin = true;
            beta = hasMax ? 0.5f * (beta + bmax) : beta * 2.f;
        } else {
            bmax = beta; hasMax = true;
            beta = hasMin ? 0.5f * (beta + bmin) : beta * 0.5f;
        }
        hbeta_eval(d, val, beta, p, Psum, H);
        Hdiff = H - logU;
    }

    // normalized contributions: p[t]/Psum in [0,1] by construction
    float c[NCAT];
    #pragma unroll
    for (int cc = 0; cc < NCAT; ++cc) c[cc] = 0.f;
    #pragma unroll
    for (int t = 0; t < 3; ++t) {
        float pv = (val[t] && Psum > 0.f) ? __fdiv_rn(p[t], Psum) : 0.f;
        int lv = lb[t];
        #pragma unroll
        for (int cc = 0; cc < NCAT; ++cc)
            c[cc] += (lv == cc) ? pv : 0.f;
    }
    float simpson = 0.f;
    #pragma unroll
    for (int cc = 0; cc < NCAT; ++cc) {
        float tot = warp_sum(c[cc]);
        simpson += tot * tot;
    }
    if (H == 0.f) simpson -= 1.f;
    if (lane == 0) out[row] = __fdiv_rn(1.f, simpson);
}

// ------------------------------------------------------------------- launch
extern "C" void kernel_launch(void* const* d_in, const int* in_sizes, int n_in,
                              void* d_out, int out_size) {
    const float* x        = (const float*)d_in[0];
    const int*   batch_id = (const int*)d_in[1];
    float*       out      = (float*)d_out;

    constexpr int GEMM_SMEM = (BM * KPAD + BN * KPAD + BM + BN) * (int)sizeof(float);
    cudaFuncSetAttribute(gemm_d2_kernel,
                         cudaFuncAttributeMaxDynamicSharedMemorySize, GEMM_SMEM);

    gemm_d2_kernel<<<dim3(NPTS / BN, NPTS / BM), 256, GEMM_SMEM>>>(x);
    select_kernel<<<NPTS, 256>>>(batch_id);
    beta_kernel<<<NPTS / 4, 128>>>(out);
}

// round 11
// speedup vs baseline: 1.7468x; 1.7468x over previous
#include <cuda_runtime.h>
#include <cstdint>
#include <cfloat>
#include <math.h>

#define NPTS 8192
#define DIM 64
#define KNN 90
#define NCAT 8
#define NTRIES 50
#define TOLR 1e-5f
#define WCAP 256     // per-warp candidate cap
#define CCAP 2048    // total candidate cap (8 warps * WCAP)

// scratch (device globals: allocation-free kernel_launch)
__device__ float g_d2[(size_t)NPTS * NPTS];   // 256 MB pairwise d2 (diagonal = FLT_MAX)
__device__ float g_dist[NPTS * KNN];
__device__ int   g_lab[NPTS * KNN];

// ---------------------------------------------------------------- GEMM stage
#define BM 128
#define BN 128
#define KPAD 65    // 64 + 1 pad: conflict-free LDS for strided frags
#define TPITCH 129 // transpose-stage pitch

// XLA-emulating row norm: jnp.sum(x*x, -1): products individually rounded
// (no fma), float2-vectorized lane partials, then shfl tree.
__device__ __forceinline__ float xla_row_sq(const float* rowp, int lane) {
    float x0 = rowp[2 * lane];
    float x1 = rowp[2 * lane + 1];
    float s = __fadd_rn(__fmul_rn(x0, x0), __fmul_rn(x1, x1));
    #pragma unroll
    for (int off = 16; off > 0; off >>= 1)
        s = __fadd_rn(s, __shfl_down_sync(0xffffffffu, s, off));
    return __shfl_sync(0xffffffffu, s, 0);
}

// Computes tile (by, bx) for bx >= by only. d2 is bitwise symmetric
// (fmaf(a,b,c)==fmaf(b,a,c); fadd commutes; same ascending-k order), so the
// off-diagonal mirror tile is written from an smem-staged transpose.
__global__ void __launch_bounds__(256, 2) gemm_d2_kernel(const float* __restrict__ x) {
    extern __shared__ float smem[];
    float* As  = smem;                    // [BM][KPAD]
    float* Bs  = smem + BM * KPAD;        // [BN][KPAD]
    float* sqA = Bs + BN * KPAD;          // [BM]
    float* sqB = sqA + BM;                // [BN]
    float* Ts  = smem;                    // transpose stage, reuses As+Bs (16512 <= 16640 floats)

    const int bx = blockIdx.x;
    const int by = blockIdx.y;
    if (by > bx) return;                  // lower triangle handled by mirror
    const bool mirror = (bx > by);

    const int tid = threadIdx.x;
    const int bm = by * BM;
    const int bn = bx * BN;

    // coalesced global load: float4 per thread, 16 threads cover one 64-col row
    const int c4 = tid & 15;
    const int rb = tid >> 4;
    #pragma unroll
    for (int it = 0; it < 8; ++it) {
        int r = rb + it * 16;
        float4 av = *reinterpret_cast<const float4*>(x + (size_t)(bm + r) * DIM + c4 * 4);
        float4 bv = *reinterpret_cast<const float4*>(x + (size_t)(bn + r) * DIM + c4 * 4);
        float* ap = As + r * KPAD + c4 * 4;
        ap[0] = av.x; ap[1] = av.y; ap[2] = av.z; ap[3] = av.w;
        float* bp = Bs + r * KPAD + c4 * 4;
        bp[0] = bv.x; bp[1] = bv.y; bp[2] = bv.z; bp[3] = bv.w;
    }
    __syncthreads();

    // norms with XLA-matching arithmetic (warp per row)
    {
        const int lane = tid & 31;
        const int wrp  = tid >> 5;
        #pragma unroll
        for (int it = 0; it < 16; ++it) {
            int r = wrp + it * 8;
            float sa = xla_row_sq(As + r * KPAD, lane);
            float sb = xla_row_sq(Bs + r * KPAD, lane);
            if (lane == 0) { sqA[r] = sa; sqB[r] = sb; }
        }
    }
    __syncthreads();

    // 8x8 micro-tile, strided mapping (row = ty+16i, col = tx+16j)
    const int tx = tid & 15;
    const int ty = tid >> 4;

    float acc[8][8];
    #pragma unroll
    for (int i = 0; i < 8; ++i)
        #pragma unroll
        for (int j = 0; j < 8; ++j) acc[i][j] = 0.f;

    // sequential ascending-k fp32 FFMA chain (reference-matching numerics)
    #pragma unroll 8
    for (int k = 0; k < DIM; ++k) {
        float a[8], b[8];
        #pragma unroll
        for (int i = 0; i < 8; ++i) a[i] = As[(ty + 16 * i) * KPAD + k];
        #pragma unroll
        for (int j = 0; j < 8; ++j) b[j] = Bs[(tx + 16 * j) * KPAD + k];
        #pragma unroll
        for (int i = 0; i < 8; ++i)
            #pragma unroll
            for (int j = 0; j < 8; ++j)
                acc[i][j] = fmaf(a[i], b[j], acc[i][j]);
    }
    __syncthreads();   // all warps done reading As/Bs before Ts staging

    #pragma unroll
    for (int i = 0; i < 8; ++i) {
        int m = ty + 16 * i;
        int gm = bm + m;
        float sm = sqA[m];
        float* orow = g_d2 + (size_t)gm * NPTS + bn;
        #pragma unroll
        for (int j = 0; j < 8; ++j) {
            int n = tx + 16 * j;
            float v = __fsub_rn(__fadd_rn(sm, sqB[n]), __fmul_rn(2.f, acc[i][j]));
            v = fmaxf(v, 0.f);
            if (gm == bn + n) v = FLT_MAX;     // exclude self (diag tiles only)
            orow[n] = v;
            if (mirror) Ts[n * TPITCH + m] = v;
        }
    }

    if (mirror) {
        __syncthreads();
        // coalesced mirror write: g_d2[(bn+r), bm+c] = Ts[r][c]
        #pragma unroll
        for (int q = 0; q < 16; ++q) {
            int idx = tid + q * 256;          // 0..4095 (128 rows x 32 float4)
            int r   = idx >> 5;
            int cc  = idx & 31;
            const float* tp = Ts + r * TPITCH + cc * 4;
            float4 v;
            v.x = tp[0]; v.y = tp[1]; v.z = tp[2]; v.w = tp[3];
            *reinterpret_cast<float4*>(g_d2 + (size_t)(bn + r) * NPTS + bm + cc * 4) = v;
        }
    }
}

// ------------------------------------------------------------- select stage
// one block per row. Sampling pivot -> ballot-compacted gather (no atomics)
// -> bitonic sort by (key, idx) == exact jax.lax.top_k order. Validated with
// retry + never-taken brute-force fallback: correct for any data.
__global__ void __launch_bounds__(256) select_kernel(const int* __restrict__ batch_id) {
    __shared__ unsigned long long candbuf[2 * CCAP];   // 32 KB (A | B)
    __shared__ unsigned samp[256];
    __shared__ unsigned wcnt[8], woff[8];
    __shared__ unsigned s_total;
    __shared__ int s_fail;
    __shared__ float wv[8];
    __shared__ int   wj[8];

    unsigned long long* candA = candbuf;
    unsigned long long* candB = candbuf + CCAP;

    const int row  = blockIdx.x;
    const int tid  = threadIdx.x;
    const int lane = tid & 31;
    const int wid  = tid >> 5;
    const unsigned* keys = reinterpret_cast<const unsigned*>(g_d2 + (size_t)row * NPTS);

    // --- 256 strided samples, bitonic-sorted ascending ---
    samp[tid] = keys[tid * 32];
    __syncthreads();
    for (int k = 2; k <= 256; k <<= 1) {
        for (int j = k >> 1; j > 0; j >>= 1) {
            int ix = tid ^ j;
            if (ix > tid) {
                unsigned a = samp[tid], b = samp[ix];
                bool up = ((tid & k) == 0);
                if ((a > b) == up) { samp[tid] = b; samp[ix] = a; }
            }
            __syncthreads();
        }
    }

    // --- gather attempts: T = 12th sample, then 48th ---
    bool ok = false;
    unsigned total = 0;
    for (int attempt = 0; attempt < 2 && !ok; ++attempt) {
        unsigned T = samp[attempt ? 47 : 11];
        if (tid == 0) s_fail = 0;
        __syncthreads();

        unsigned cnt = 0;
        bool ovf = false;
        for (int it = 0; it < 32; ++it) {
            int j = wid * 1024 + it * 32 + lane;
            unsigned key = keys[j];
            bool pred = (key <= T);
            unsigned mask = __ballot_sync(0xffffffffu, pred);
            unsigned rnk = __popc(mask & ((1u << lane) - 1u));
            unsigned n   = __popc(mask);
            if (pred && cnt + rnk < WCAP)
                candA[wid * WCAP + cnt + rnk] =
                    ((unsigned long long)key << 32) | (unsigned)j;
            if (cnt + n > WCAP) ovf = true;
            cnt = min(cnt + n, (unsigned)WCAP);
        }
        if (lane == 0) { wcnt[wid] = cnt; if (ovf) s_fail = 1; }
        __syncthreads();
        if (tid == 0) {
            unsigned off = 0;
            #pragma unroll
            for (int w = 0; w < 8; ++w) { woff[w] = off; off += wcnt[w]; }
            s_total = off;
        }
        __syncthreads();
        total = s_total;
        ok = (s_fail == 0 && total >= KNN);   // total <= CCAP by construction
        if (ok) {
            for (unsigned t = lane; t < wcnt[wid]; t += 32)
                candB[woff[wid] + t] = candA[wid * WCAP + t];
        }
        __syncthreads();
    }

    if (ok) {
        // pad to pow2 and bitonic sort ascending by (key, idx)
        int sortN = 128;
        while (sortN < (int)total) sortN <<= 1;
        for (int i = tid; i < sortN; i += 256)
            if (i >= (int)total) candB[i] = 0xFFFFFFFFFFFFFFFFull;
        __syncthreads();
        for (int k = 2; k <= sortN; k <<= 1) {
            for (int j = k >> 1; j > 0; j >>= 1) {
                for (int i = tid; i < sortN; i += 256) {
                    int ix = i ^ j;
                    if (ix > i) {
                        unsigned long long a = candB[i], b = candB[ix];
                        bool up = ((i & k) == 0);
                        if ((a > b) == up) { candB[i] = b; candB[ix] = a; }
                    }
                }
                __syncthreads();
            }
        }
        if (tid < KNN) {
            unsigned long long v = candB[tid];
            unsigned key = (unsigned)(v >> 32);
            int idx = (int)(v & 0xFFFFFFFFu);
            g_dist[row * KNN + tid] = __fsqrt_rn(__uint_as_float(key));
            g_lab[row * KNN + tid]  = batch_id[idx];
        }
        return;
    }

    // --- brute-force fallback (degenerate data only; never taken in practice) ---
    {
        unsigned* skey = reinterpret_cast<unsigned*>(candbuf);   // 8192 keys = 32KB
        for (int it = 0; it < 32; ++it) {
            int q = tid + it * 256;
            skey[q] = keys[q];
        }
        __syncthreads();
        for (int p = 0; p < KNN; ++p) {
            float bv = FLT_MAX; int bj = NPTS;
            for (int it = 0; it < 32; ++it) {
                int j = it * 256 + tid;
                float v = __uint_as_float(skey[j]);
                if (v < bv) { bv = v; bj = j; }
            }
            #pragma unroll
            for (int off = 16; off > 0; off >>= 1) {
                float ov = __shfl_xor_sync(0xffffffffu, bv, off);
                int   oj = __shfl_xor_sync(0xffffffffu, bj, off);
                if (ov < bv || (ov == bv && oj < bj)) { bv = ov; bj = oj; }
            }
            if (lane == 0) { wv[wid] = bv; wj[wid] = bj; }
            __syncthreads();
            if (tid == 0) {
                float fv = wv[0]; int fj = wj[0];
                #pragma unroll
                for (int w = 1; w < 8; ++w)
                    if (wv[w] < fv || (wv[w] == fv && wj[w] < fj)) { fv = wv[w]; fj = wj[w]; }
                skey[fj] = __float_as_uint(FLT_MAX);
                g_dist[row * KNN + p] = __fsqrt_rn(fv);
                g_lab[row * KNN + p]  = batch_id[fj];
            }
            __syncthreads();
        }
    }
}

// --------------------------------------------------------- beta search stage
__device__ __forceinline__ float warp_sum(float v) {
    #pragma unroll
    for (int o = 16; o > 0; o >>= 1) v += __shfl_xor_sync(0xffffffffu, v, o);
    return v;
}

// FTZ exp: XLA compiles GPU f32 with flush-to-zero — exp results that would be
// subnormal flush to 0. Load-bearing: rows whose solution beta sits past the
// subnormal cliff hit Psum==0 -> H==0 sentinel in the reference.
__device__ __forceinline__ float exp_ftz(float a) {
    float v = expf(a);
    if (v < 1.17549435e-38f) v = 0.f;
    return v;
}

__device__ __forceinline__ void hbeta_eval(const float d[3], const bool val[3],
                                           float beta, float p[3],
                                           float& Psum, float& H) {
    float ls = 0.f, lds = 0.f;
    #pragma unroll
    for (int t = 0; t < 3; ++t) {
        float pv = val[t] ? exp_ftz(-d[t] * beta) : 0.f;
        p[t] = pv;
        ls  += pv;
        lds += d[t] * pv;
    }
    Psum   = warp_sum(ls);
    float S = warp_sum(lds);
    H = (Psum > 0.f) ? (logf(Psum) + beta * __fdiv_rn(S, Psum)) : 0.f;
}

__global__ void __launch_bounds__(128) beta_kernel(float* __restrict__ out) {
    const int warp = threadIdx.x >> 5;
    const int lane = threadIdx.x & 31;
    const int row  = blockIdx.x * 4 + warp;

    float d[3]; int lb[3]; bool val[3];
    #pragma unroll
    for (int t = 0; t < 3; ++t) {
        int kk = lane + 32 * t;
        val[t] = (kk < KNN);
        d[t]  = val[t] ? g_dist[row * KNN + kk] : 0.f;
        lb[t] = val[t] ? g_lab[row * KNN + kk]  : -1;
    }

    const float logU = logf(30.0f);
    float beta = 1.f, bmin = 0.f, bmax = 0.f;
    bool hasMin = false, hasMax = false;
    float p[3], Psum, H;

    hbeta_eval(d, val, beta, p, Psum, H);
    float Hdiff = H - logU;
    for (int it = 0; it < NTRIES; ++it) {
        if (fabsf(Hdiff) < TOLR) break;
        if (Hdiff > 0.f) {
            bmin = beta; hasMin = true;
            beta = hasMax ? 0.5f * (beta + bmax) : beta * 2.f;
        } else {
            bmax = beta; hasMax = true;
            beta = hasMin ? 0.5f * (beta + bmin) : beta * 0.5f;
        }
        hbeta_eval(d, val, beta, p, Psum, H);
        Hdiff = H - logU;
    }

    float c[NCAT];
    #pragma unroll
    for (int cc = 0; cc < NCAT; ++cc) c[cc] = 0.f;
    #pragma unroll
    for (int t = 0; t < 3; ++t) {
        float pv = (val[t] && Psum > 0.f) ? __fdiv_rn(p[t], Psum) : 0.f;
        int lv = lb[t];
        #pragma unroll
        for (int cc = 0; cc < NCAT; ++cc)
            c[cc] += (lv == cc) ? pv : 0.f;
    }
    float simpson = 0.f;
    #pragma unroll
    for (int cc = 0; cc < NCAT; ++cc) {
        float tot = warp_sum(c[cc]);
        simpson += tot * tot;
    }
    if (H == 0.f) simpson -= 1.f;
    if (lane == 0) out[row] = __fdiv_rn(1.f, simpson);
}

// ------------------------------------------------------------------- launch
extern "C" void kernel_launch(void* const* d_in, const int* in_sizes, int n_in,
                              void* d_out, int out_size) {
    const float* x        = (const float*)d_in[0];
    const int*   batch_id = (const int*)d_in[1];
    float*       out      = (float*)d_out;

    constexpr int GEMM_SMEM = (BM * KPAD + BN * KPAD + BM + BN) * (int)sizeof(float);
    cudaFuncSetAttribute(gemm_d2_kernel,
                         cudaFuncAttributeMaxDynamicSharedMemorySize, GEMM_SMEM);

    gemm_d2_kernel<<<dim3(NPTS / BN, NPTS / BM), 256, GEMM_SMEM>>>(x);
    select_kernel<<<NPTS, 256>>>(batch_id);
    beta_kernel<<<NPTS / 4, 128>>>(out);
}